// round 10
// baseline (speedup 1.0000x reference)
#include <cuda_runtime.h>

#define NF 255
#define NH 128
#define NC 16
#define NIMG 64
#define PI2 6.28318530717958647692f
typedef unsigned long long u64;

__device__ __forceinline__ void fma2(u64 &d, u64 a, u64 b){
    asm("fma.rn.f32x2 %0, %1, %2, %0;" : "+l"(d) : "l"(a), "l"(b));
}
__device__ __forceinline__ u64 pk2(float lo, float hi){
    u64 r; asm("mov.b64 %0, {%1,%2};" : "=l"(r) : "f"(lo), "f"(hi)); return r;
}
__device__ __forceinline__ float2 up2(u64 v){
    float2 f; asm("mov.b64 {%0,%1}, %2;" : "=f"(f.x), "=f"(f.y) : "l"(v)); return f;
}

// scratch (device globals: allocation-free rule)
__device__ float2 g_Fp[NF*NH];          // (cos,-sin)[v*128+h]
__device__ float2 g_Gp[NH*NF];          // (cos, sin)[w'*255+v], crop +63
__device__ float2 g_E2r[NH*NH];         // (Er,Er)   Er=cu*cos
__device__ float2 g_E2n[NH*NH];         // (-Ei,-Ei) Ei=cu*sin
__device__ float  g_xT[NIMG*NH*NH];     // [img][w][h]
__device__ float2 g_A0[NIMG*NH*NH], g_A1[NIMG*NH*NH];     // stage1 partials
__device__ float2 g_Xf0[NIMG*NH*NF], g_Xf1[NIMG*NH*NF];   // stage2 partials
__device__ float2 g_Kh[NC*NH*NF];       // [c][u][v] folded, scaled
__device__ float2 g_St0[NIMG*NH*NH], g_St1[NIMG*NH*NH];   // stage3 partials (transposed)

__global__ void k_twiddles(){
    int i = blockIdx.x*blockDim.x + threadIdx.x;
    const float w0 = PI2/255.0f;
    if(i < NF*NH){
        int v=i/NH, h=i%NH; float a=w0*(float)((v*h)%NF);
        g_Fp[i]=make_float2(cosf(a),-sinf(a)); return;
    }
    int j=i-NF*NH;
    if(j < NH*NF){
        int wq=j/NF, v=j%NF; float a=w0*(float)((v*(wq+63))%NF);
        g_Gp[j]=make_float2(cosf(a),sinf(a)); return;
    }
    int e=j-NH*NF;
    if(e < NH*NH){
        int h=e/NH, u=e%NH; float a=w0*(float)((u*(h+63))%NF);
        float cu = u?2.f:1.f, er=cu*cosf(a), ei=cu*sinf(a);
        g_E2r[e]=make_float2(er,er); g_E2n[e]=make_float2(-ei,-ei);
    }
}

// in[b][h][w][c] -> g_xT[(b*16+c)][w][h], smem-staged
__global__ void k_transpose(const float* __restrict__ in){
    __shared__ float ts[NC*16*36];
    const int b=blockIdx.z, h0=blockIdx.y*32, w0=blockIdx.x*16, tid=threadIdx.x;
#pragma unroll
    for(int it=0;it<2;it++){
        int p=tid+it*256, h=p>>4, w=p&15;
        const float4* src=(const float4*)(in+(size_t)((b*NH+h0+h)*NH+w0+w)*NC);
#pragma unroll
        for(int q=0;q<4;q++){
            float4 v=src[q]; int cb=q*4;
            ts[(cb+0)*576+w*36+h]=v.x; ts[(cb+1)*576+w*36+h]=v.y;
            ts[(cb+2)*576+w*36+h]=v.z; ts[(cb+3)*576+w*36+h]=v.w;
        }
    }
    __syncthreads();
    int h4=(tid&7)*4;
#pragma unroll
    for(int it=0;it<8;it++){
        int q=(tid>>3)+it*32, c=q>>4, w=q&15;
        float4 v=*(const float4*)&ts[c*576+w*36+h4];
        *(float4*)&g_xT[(size_t)((b*NC+c)*NH+w0+w)*NH+h0+h4]=v;
    }
}

// fused Keff (sum over cout) + Hermitian fold + 1/255^2 scale
__global__ void k_keffkh(const float* __restrict__ kr, const float* __restrict__ ki){
    int idx = blockIdx.x*blockDim.x + threadIdx.x;
    if(idx >= NH*NF*NC) return;
    int c = idx&15, v = (idx>>4)%NF, u = idx/(16*NF);
    int u2=(NF-u)%NF, v2=(NF-v)%NF;
    size_t p1=((size_t)(u*NF+v)*NC+c)*16, p2=((size_t)(u2*NF+v2)*NC+c)*16;
    float sr1=0,si1=0,sr2=0,si2=0; const float4* a;
    a=(const float4*)(kr+p1);
#pragma unroll
    for(int j=0;j<4;j++){float4 t=a[j];sr1+=t.x+t.y+t.z+t.w;}
    a=(const float4*)(ki+p1);
#pragma unroll
    for(int j=0;j<4;j++){float4 t=a[j];si1+=t.x+t.y+t.z+t.w;}
    a=(const float4*)(kr+p2);
#pragma unroll
    for(int j=0;j<4;j++){float4 t=a[j];sr2+=t.x+t.y+t.z+t.w;}
    a=(const float4*)(ki+p2);
#pragma unroll
    for(int j=0;j<4;j++){float4 t=a[j];si2+=t.x+t.y+t.z+t.w;}
    const float s = 0.5f/65025.0f;
    g_Kh[(c*NH+u)*NF+v]=make_float2(s*(sr1+sr2), s*(si1-si2));
}

// ---------------------------------------------------------------------------
// GEMM: BM=64, BN=64, BK=16, 128 thr, 8m x 4n packed microtile, reg-prefetch.
// Stages 1-3 K-split across 2 CTAs (blockIdx.z = img*2+half) into partial
// buffers; the partial add is folded into the NEXT stage's tile loads.
// ---------------------------------------------------------------------------
#define A_PITCH 164
#define B_PITCH 196
__device__ __forceinline__ int aoff(int k,int m){ return k*A_PITCH+(m>>3)*20+(m&7)*2; }
__device__ __forceinline__ int boff(int k,int n){ return k*B_PITCH+(n>>2)*12+(n&3)*2; }

__device__ __forceinline__ void cplx_inner(const float* ARR,const float* ANP,
        const float* BP,const float* BS, u64 (&acc)[8][4], int tm, int tn){
#pragma unroll 4
    for(int k=0;k<16;k++){
        u64 aR[8],aN[8],bP[4],bS[4];
        const ulonglong2* p1=(const ulonglong2*)&ARR[k*A_PITCH+tm*20];
        const ulonglong2* p2=(const ulonglong2*)&ANP[k*A_PITCH+tm*20];
        const ulonglong2* p3=(const ulonglong2*)&BP [k*B_PITCH+tn*12];
        const ulonglong2* p4=(const ulonglong2*)&BS [k*B_PITCH+tn*12];
#pragma unroll
        for(int q=0;q<4;q++){
            ulonglong2 t=p1[q]; aR[2*q]=t.x; aR[2*q+1]=t.y;
            ulonglong2 s=p2[q]; aN[2*q]=s.x; aN[2*q+1]=s.y;
        }
        { ulonglong2 t=p3[0]; bP[0]=t.x; bP[1]=t.y; t=p3[1]; bP[2]=t.x; bP[3]=t.y;
          t=p4[0]; bS[0]=t.x; bS[1]=t.y; t=p4[1]; bS[2]=t.x; bS[3]=t.y; }
#pragma unroll
        for(int i=0;i<8;i++)
#pragma unroll
            for(int j=0;j<4;j++){ fma2(acc[i][j],aR[i],bP[j]); fma2(acc[i][j],aN[i],bS[j]); }
    }
}

// Stage1: Apart[half][img][u][w] = sum_{h in half} F[u][h]*x[img][w][h]
__global__ void __launch_bounds__(128) k_stage1(){
    __shared__ __align__(16) float AP[16*A_PITCH];
    __shared__ __align__(16) float BD[16*B_PITCH];
    const int kz=blockIdx.z, img=kz>>1, half=kz&1, kb=half*64;
    const int n0=blockIdx.x*64, m0=blockIdx.y*64, tid=threadIdx.x;
    const int tn=tid&15, tm=tid>>4, lk=tid&15, lr=tid>>4;
    const float* Bg = g_xT + img*NH*NH;
    u64 acc[8][4];
#pragma unroll
    for(int i=0;i<8;i++)
#pragma unroll
        for(int j=0;j<4;j++) acc[i][j]=0ULL;
    float2 pa[8]; float pbx[8];
#pragma unroll
    for(int r=0;r<8;r++) pa[r]=g_Fp[(m0+lr+r*8)*NH+kb+lk];
#pragma unroll
    for(int r=0;r<8;r++) pbx[r]=Bg[(n0+lr+r*8)*NH+kb+lk];
    for(int t=0;t<4;t++){
#pragma unroll
        for(int r=0;r<8;r++) *(float2*)&AP[aoff(lk,lr+r*8)]=pa[r];
#pragma unroll
        for(int r=0;r<8;r++) *(float2*)&BD[boff(lk,lr+r*8)]=make_float2(pbx[r],pbx[r]);
        __syncthreads();
        if(t<3){
            int k0=kb+(t+1)*16;
#pragma unroll
            for(int r=0;r<8;r++) pa[r]=g_Fp[(m0+lr+r*8)*NH+k0+lk];
#pragma unroll
            for(int r=0;r<8;r++) pbx[r]=Bg[(n0+lr+r*8)*NH+k0+lk];
        }
#pragma unroll 4
        for(int k=0;k<16;k++){
            u64 aP[8],bD[4];
            const ulonglong2* p1=(const ulonglong2*)&AP[k*A_PITCH+tm*20];
            const ulonglong2* p3=(const ulonglong2*)&BD[k*B_PITCH+tn*12];
#pragma unroll
            for(int q=0;q<4;q++){ ulonglong2 t2=p1[q]; aP[2*q]=t2.x; aP[2*q+1]=t2.y; }
            { ulonglong2 t2=p3[0]; bD[0]=t2.x; bD[1]=t2.y; t2=p3[1]; bD[2]=t2.x; bD[3]=t2.y; }
#pragma unroll
            for(int i=0;i<8;i++)
#pragma unroll
                for(int j=0;j<4;j++) fma2(acc[i][j],aP[i],bD[j]);
        }
        __syncthreads();
    }
    float2* C = (half ? g_A1 : g_A0) + img*NH*NH;
#pragma unroll
    for(int i=0;i<8;i++){ int m=m0+tm*8+i;
#pragma unroll
        for(int j=0;j<4;j++) C[m*NH+n0+tn*4+j]=up2(acc[i][j]); }
}

// Stage2: Xfpart[half][img][u][v] = sum_{w in half} (A0+A1)[img][u][w]*F[v][w]
__global__ void __launch_bounds__(128) k_stage2(){
    __shared__ __align__(16) float ARR[16*A_PITCH];
    __shared__ __align__(16) float ANP[16*A_PITCH];
    __shared__ __align__(16) float BP [16*B_PITCH];
    __shared__ __align__(16) float BS [16*B_PITCH];
    const int kz=blockIdx.z, img=kz>>1, half=kz&1, kb=half*64;
    const int n0=blockIdx.x*64, m0=blockIdx.y*64, tid=threadIdx.x;
    const int tn=tid&15, tm=tid>>4, lk=tid&15, lr=tid>>4;
    const float2* Ag0 = g_A0 + img*NH*NH;
    const float2* Ag1 = g_A1 + img*NH*NH;
    u64 acc[8][4];
#pragma unroll
    for(int i=0;i<8;i++)
#pragma unroll
        for(int j=0;j<4;j++) acc[i][j]=0ULL;
    float2 pa[8], pb[8];
#pragma unroll
    for(int r=0;r<8;r++){ int off=(m0+lr+r*8)*NH+kb+lk;
        float2 a0=Ag0[off], a1=Ag1[off];
        pa[r]=make_float2(a0.x+a1.x, a0.y+a1.y); }
#pragma unroll
    for(int r=0;r<8;r++){ int v=n0+lr+r*8;
        pb[r]=(v<NF)? g_Fp[v*NH+kb+lk] : make_float2(0.f,0.f); }
    for(int t=0;t<4;t++){
#pragma unroll
        for(int r=0;r<8;r++){ int m=lr+r*8;
            *(float2*)&ARR[aoff(lk,m)]=make_float2(pa[r].x,pa[r].x);
            *(float2*)&ANP[aoff(lk,m)]=make_float2(-pa[r].y,pa[r].y); }
#pragma unroll
        for(int r=0;r<8;r++){ int n=lr+r*8;
            *(float2*)&BP[boff(lk,n)]=pb[r];
            *(float2*)&BS[boff(lk,n)]=make_float2(pb[r].y,pb[r].x); }
        __syncthreads();
        if(t<3){
            int k0=kb+(t+1)*16;
#pragma unroll
            for(int r=0;r<8;r++){ int off=(m0+lr+r*8)*NH+k0+lk;
                float2 a0=Ag0[off], a1=Ag1[off];
                pa[r]=make_float2(a0.x+a1.x, a0.y+a1.y); }
#pragma unroll
            for(int r=0;r<8;r++){ int v=n0+lr+r*8;
                pb[r]=(v<NF)? g_Fp[v*NH+k0+lk] : make_float2(0.f,0.f); }
        }
        cplx_inner(ARR,ANP,BP,BS,acc,tm,tn);
        __syncthreads();
    }
    float2* C = (half ? g_Xf1 : g_Xf0) + img*NH*NF;
#pragma unroll
    for(int i=0;i<8;i++){ int m=m0+tm*8+i;
#pragma unroll
        for(int j=0;j<4;j++){ int n=n0+tn*4+j;
            if(n<NF) C[m*NF+n]=up2(acc[i][j]); } }
}

// Stage3: Stpart[half][img][w'][u] = sum_{v in half} ((Xf0+Xf1)[u][v]*Kh[c][u][v])*G[w'][v]
__global__ void __launch_bounds__(128) k_stage3(){
    __shared__ __align__(16) float ARR[16*A_PITCH];
    __shared__ __align__(16) float ANP[16*A_PITCH];
    __shared__ __align__(16) float BP [16*B_PITCH];
    __shared__ __align__(16) float BS [16*B_PITCH];
    const int kz=blockIdx.z, img=kz>>1, half=kz&1, kb=half*128;
    const int c=img&15, n0=blockIdx.x*64, m0=blockIdx.y*64, tid=threadIdx.x;
    const int tn=tid&15, tm=tid>>4, lk=tid&15, lr=tid>>4;
    const float2* Xg0 = g_Xf0 + img*NH*NF;
    const float2* Xg1 = g_Xf1 + img*NH*NF;
    const float2* Kg = g_Kh + c*NH*NF;
    u64 acc[8][4];
#pragma unroll
    for(int i=0;i<8;i++)
#pragma unroll
        for(int j=0;j<4;j++) acc[i][j]=0ULL;
    float2 py[8], pb[8];
    {
        int kk=kb+lk; bool ok=(kk<NF);
#pragma unroll
        for(int r=0;r<8;r++){
            float yr=0.f, yi=0.f;
            if(ok){ int off=(m0+lr+r*8)*NF+kk;
                float2 x0=Xg0[off], x1=Xg1[off], h=Kg[off];
                float xr=x0.x+x1.x, xi=x0.y+x1.y;
                yr=xr*h.x-xi*h.y; yi=xr*h.y+xi*h.x; }
            py[r]=make_float2(yr,yi);
        }
#pragma unroll
        for(int r=0;r<8;r++)
            pb[r]= ok ? g_Gp[(n0+lr+r*8)*NF+kk] : make_float2(0.f,0.f);
    }
    for(int t=0;t<8;t++){
#pragma unroll
        for(int r=0;r<8;r++){ int m=lr+r*8;
            *(float2*)&ARR[aoff(lk,m)]=make_float2(py[r].x,py[r].x);
            *(float2*)&ANP[aoff(lk,m)]=make_float2(-py[r].y,py[r].y); }
#pragma unroll
        for(int r=0;r<8;r++){ int n=lr+r*8;
            *(float2*)&BP[boff(lk,n)]=pb[r];
            *(float2*)&BS[boff(lk,n)]=make_float2(pb[r].y,pb[r].x); }
        __syncthreads();
        if(t<7){
            int kk=kb+(t+1)*16+lk; bool ok=(kk<NF);
#pragma unroll
            for(int r=0;r<8;r++){
                float yr=0.f, yi=0.f;
                if(ok){ int off=(m0+lr+r*8)*NF+kk;
                    float2 x0=Xg0[off], x1=Xg1[off], h=Kg[off];
                    float xr=x0.x+x1.x, xi=x0.y+x1.y;
                    yr=xr*h.x-xi*h.y; yi=xr*h.y+xi*h.x; }
                py[r]=make_float2(yr,yi);
            }
#pragma unroll
            for(int r=0;r<8;r++)
                pb[r]= ok ? g_Gp[(n0+lr+r*8)*NF+kk] : make_float2(0.f,0.f);
        }
        cplx_inner(ARR,ANP,BP,BS,acc,tm,tn);
        __syncthreads();
    }
    float2* C = (half ? g_St1 : g_St0) + img*NH*NH;
#pragma unroll
    for(int i=0;i<8;i++){ int m=m0+tm*8+i;
#pragma unroll
        for(int j=0;j<4;j++){ int n=n0+tn*4+j;
            C[n*NH+m]=up2(acc[i][j]); } }   // transposed store
}

// Stage4: out = bias + sum_u (Er*(S0+S1).r - Ei*(S0+S1).i)
__global__ void __launch_bounds__(128) k_stage4(const float* __restrict__ bias,
                                               float* __restrict__ out){
    __shared__ __align__(16) float AE[16*A_PITCH];
    __shared__ __align__(16) float AN[16*A_PITCH];
    __shared__ __align__(16) float BR[16*68];
    __shared__ __align__(16) float BI[16*68];
    const int img=blockIdx.z, b2=img>>4, c=img&15;
    const int n0=blockIdx.x*64, m0=blockIdx.y*64, tid=threadIdx.x;
    const int tn=tid&15, tm=tid>>4, lk=tid&15, lr=tid>>4;
    const float2* Sg0 = g_St0 + img*NH*NH;
    const float2* Sg1 = g_St1 + img*NH*NH;
    u64 acc[8][2];
#pragma unroll
    for(int i=0;i<8;i++){ acc[i][0]=0ULL; acc[i][1]=0ULL; }
    float2 pe[8], pn[8], ps[8];
#pragma unroll
    for(int r=0;r<8;r++){ int m=m0+lr+r*8;
        pe[r]=g_E2r[m*NH+lk]; pn[r]=g_E2n[m*NH+lk]; }
#pragma unroll
    for(int r=0;r<8;r++){ int off=(n0+lr+r*8)*NH+lk;
        float2 s0=Sg0[off], s1=Sg1[off];
        ps[r]=make_float2(s0.x+s1.x, s0.y+s1.y); }
    for(int t=0;t<8;t++){
#pragma unroll
        for(int r=0;r<8;r++){ int m=lr+r*8;
            *(float2*)&AE[aoff(lk,m)]=pe[r];
            *(float2*)&AN[aoff(lk,m)]=pn[r]; }
#pragma unroll
        for(int r=0;r<8;r++){ int n=lr+r*8;
            BR[lk*68+n]=ps[r].x; BI[lk*68+n]=ps[r].y; }
        __syncthreads();
        if(t<7){
            int k0=(t+1)*16;
#pragma unroll
            for(int r=0;r<8;r++){ int m=m0+lr+r*8;
                pe[r]=g_E2r[m*NH+k0+lk]; pn[r]=g_E2n[m*NH+k0+lk]; }
#pragma unroll
            for(int r=0;r<8;r++){ int off=(n0+lr+r*8)*NH+k0+lk;
                float2 s0=Sg0[off], s1=Sg1[off];
                ps[r]=make_float2(s0.x+s1.x, s0.y+s1.y); }
        }
#pragma unroll 4
        for(int k=0;k<16;k++){
            u64 aE[8],aN2[8];
            const ulonglong2* p1=(const ulonglong2*)&AE[k*A_PITCH+tm*20];
            const ulonglong2* p2=(const ulonglong2*)&AN[k*A_PITCH+tm*20];
#pragma unroll
            for(int q=0;q<4;q++){
                ulonglong2 t2=p1[q]; aE[2*q]=t2.x; aE[2*q+1]=t2.y;
                ulonglong2 s2=p2[q]; aN2[2*q]=s2.x; aN2[2*q+1]=s2.y; }
            float4 br=*(const float4*)&BR[k*68+tn*4];
            float4 bi=*(const float4*)&BI[k*68+tn*4];
            u64 b0=pk2(br.x,br.y), b1=pk2(br.z,br.w);
            u64 c0=pk2(bi.x,bi.y), c1=pk2(bi.z,bi.w);
#pragma unroll
            for(int i=0;i<8;i++){
                fma2(acc[i][0],aE[i],b0); fma2(acc[i][0],aN2[i],c0);
                fma2(acc[i][1],aE[i],b1); fma2(acc[i][1],aN2[i],c1);
            }
        }
        __syncthreads();
    }
    float bv = bias[c];
#pragma unroll
    for(int i=0;i<8;i++){ int h=m0+tm*8+i;
#pragma unroll
        for(int j2=0;j2<2;j2++){
            float2 p=up2(acc[i][j2]);
            int w=n0+tn*4+j2*2;
            out[((size_t)((b2*NH+h)*NH+w  ))*NC+c]=p.x+bv;
            out[((size_t)((b2*NH+h)*NH+w+1))*NC+c]=p.y+bv;
        } }
}

extern "C" void kernel_launch(void* const* d_in, const int* in_sizes, int n_in,
                              void* d_out, int out_size){
    const float* inp  = (const float*)d_in[0];
    const float* kr   = (const float*)d_in[1];
    const float* ki   = (const float*)d_in[2];
    const float* bias = (const float*)d_in[3];
    float* out = (float*)d_out;

    const int twN = NF*NH + NH*NF + NH*NH;
    k_twiddles<<<(twN+255)/256, 256>>>();
    dim3 tg(8,4,4);
    k_transpose<<<tg, 256>>>(inp);
    k_keffkh<<<(NH*NF*NC+255)/256, 256>>>(kr, ki);

    dim3 blk(128);
    dim3 g1(2,2,NIMG*2); k_stage1<<<g1, blk>>>();
    dim3 g2(4,2,NIMG*2); k_stage2<<<g2, blk>>>();
    dim3 g3(2,2,NIMG*2); k_stage3<<<g3, blk>>>();
    dim3 g4(2,2,NIMG);   k_stage4<<<g4, blk>>>(bias, out);
}

// round 11
// speedup vs baseline: 1.1388x; 1.1388x over previous
#include <cuda_runtime.h>

#define NF 255
#define NH 128
#define NC 16
#define NIMG 64
#define PI2 6.28318530717958647692f
typedef unsigned long long u64;

__device__ __forceinline__ void fma2(u64 &d, u64 a, u64 b){
    asm("fma.rn.f32x2 %0, %1, %2, %0;" : "+l"(d) : "l"(a), "l"(b));
}
__device__ __forceinline__ u64 pk2(float lo, float hi){
    u64 r; asm("mov.b64 %0, {%1,%2};" : "=l"(r) : "f"(lo), "f"(hi)); return r;
}
__device__ __forceinline__ float2 up2(u64 v){
    float2 f; asm("mov.b64 {%0,%1}, %2;" : "=f"(f.x), "=f"(f.y) : "l"(v)); return f;
}

// scratch (device globals: allocation-free rule)
__device__ float2 g_Fp[NF*NH];          // (cos,-sin)[v*128+h]
__device__ float2 g_Gp[NH*NF];          // (cos, sin)[w'*255+v], crop +63
__device__ float2 g_E2r[NH*NH];         // (Er,Er)   Er=cu*cos
__device__ float2 g_E2n[NH*NH];         // (-Ei,-Ei) Ei=cu*sin
__device__ float  g_xT[NIMG*NH*NH];     // [img][w][h]
__device__ float2 g_A [NIMG*NH*NH];     // [img][u][w]
__device__ float2 g_Xf[NIMG*NH*NF];     // [img][u][v]
__device__ float2 g_Kh[NC*NH*NF];       // [c][u][v] folded, scaled
__device__ float2 g_St[NIMG*NH*NH];     // [img][w'][u] (transposed)

__global__ void k_twiddles(){
    int i = blockIdx.x*blockDim.x + threadIdx.x;
    const float w0 = PI2/255.0f;
    if(i < NF*NH){
        int v=i/NH, h=i%NH; float a=w0*(float)((v*h)%NF);
        g_Fp[i]=make_float2(cosf(a),-sinf(a)); return;
    }
    int j=i-NF*NH;
    if(j < NH*NF){
        int wq=j/NF, v=j%NF; float a=w0*(float)((v*(wq+63))%NF);
        g_Gp[j]=make_float2(cosf(a),sinf(a)); return;
    }
    int e=j-NH*NF;
    if(e < NH*NH){
        int h=e/NH, u=e%NH; float a=w0*(float)((u*(h+63))%NF);
        float cu = u?2.f:1.f, er=cu*cosf(a), ei=cu*sinf(a);
        g_E2r[e]=make_float2(er,er); g_E2n[e]=make_float2(-ei,-ei);
    }
}

// in[b][h][w][c] -> g_xT[(b*16+c)][w][h], smem-staged
__global__ void k_transpose(const float* __restrict__ in){
    __shared__ float ts[NC*16*36];
    const int b=blockIdx.z, h0=blockIdx.y*32, w0=blockIdx.x*16, tid=threadIdx.x;
#pragma unroll
    for(int it=0;it<2;it++){
        int p=tid+it*256, h=p>>4, w=p&15;
        const float4* src=(const float4*)(in+(size_t)((b*NH+h0+h)*NH+w0+w)*NC);
#pragma unroll
        for(int q=0;q<4;q++){
            float4 v=src[q]; int cb=q*4;
            ts[(cb+0)*576+w*36+h]=v.x; ts[(cb+1)*576+w*36+h]=v.y;
            ts[(cb+2)*576+w*36+h]=v.z; ts[(cb+3)*576+w*36+h]=v.w;
        }
    }
    __syncthreads();
    int h4=(tid&7)*4;
#pragma unroll
    for(int it=0;it<8;it++){
        int q=(tid>>3)+it*32, c=q>>4, w=q&15;
        float4 v=*(const float4*)&ts[c*576+w*36+h4];
        *(float4*)&g_xT[(size_t)((b*NC+c)*NH+w0+w)*NH+h0+h4]=v;
    }
}

// fused Keff (sum over cout) + Hermitian fold + 1/255^2 scale
__global__ void k_keffkh(const float* __restrict__ kr, const float* __restrict__ ki){
    int idx = blockIdx.x*blockDim.x + threadIdx.x;
    if(idx >= NH*NF*NC) return;
    int c = idx&15, v = (idx>>4)%NF, u = idx/(16*NF);
    int u2=(NF-u)%NF, v2=(NF-v)%NF;
    size_t p1=((size_t)(u*NF+v)*NC+c)*16, p2=((size_t)(u2*NF+v2)*NC+c)*16;
    float sr1=0,si1=0,sr2=0,si2=0; const float4* a;
    a=(const float4*)(kr+p1);
#pragma unroll
    for(int j=0;j<4;j++){float4 t=a[j];sr1+=t.x+t.y+t.z+t.w;}
    a=(const float4*)(ki+p1);
#pragma unroll
    for(int j=0;j<4;j++){float4 t=a[j];si1+=t.x+t.y+t.z+t.w;}
    a=(const float4*)(kr+p2);
#pragma unroll
    for(int j=0;j<4;j++){float4 t=a[j];sr2+=t.x+t.y+t.z+t.w;}
    a=(const float4*)(ki+p2);
#pragma unroll
    for(int j=0;j<4;j++){float4 t=a[j];si2+=t.x+t.y+t.z+t.w;}
    const float s = 0.5f/65025.0f;
    g_Kh[(c*NH+u)*NF+v]=make_float2(s*(sr1+sr2), s*(si1-si2));
}

// ---------------------------------------------------------------------------
// GEMM: BM=64, BN=64, BK=16, 128 thr, 8m x 4n packed microtile, reg-prefetch.
// Stages 2/3 use Karatsuba complex: 48 fma2/thread/k instead of 64.
// ---------------------------------------------------------------------------
#define A_PITCH 164
#define B_PITCH 196
#define SB_PITCH 68
__device__ __forceinline__ int aoff(int k,int m){ return k*A_PITCH+(m>>3)*20+(m&7)*2; }
__device__ __forceinline__ int boff(int k,int n){ return k*B_PITCH+(n>>2)*12+(n&3)*2; }

// Karatsuba inner: accP[i][j] += (ar,ai)_i (x) (br,bi)_j ; accQ[i][jj] += (sa,sa)_i (x) (sb2jj,sb2jj+1)
__device__ __forceinline__ void kara_inner(const float* ACP,const float* ASD,
        const float* BCP,const float* SBV,
        u64 (&accP)[8][4], u64 (&accQ)[8][2], int tm, int tn){
#pragma unroll 4
    for(int k=0;k<16;k++){
        u64 aC[8],aS[8],bC[4],q[2];
        const ulonglong2* p1=(const ulonglong2*)&ACP[k*A_PITCH+tm*20];
        const ulonglong2* p2=(const ulonglong2*)&ASD[k*A_PITCH+tm*20];
        const ulonglong2* p3=(const ulonglong2*)&BCP[k*B_PITCH+tn*12];
        const ulonglong2* p4=(const ulonglong2*)&SBV[k*SB_PITCH+tn*4];
#pragma unroll
        for(int r=0;r<4;r++){
            ulonglong2 t=p1[r]; aC[2*r]=t.x; aC[2*r+1]=t.y;
            ulonglong2 s=p2[r]; aS[2*r]=s.x; aS[2*r+1]=s.y;
        }
        { ulonglong2 t=p3[0]; bC[0]=t.x; bC[1]=t.y; t=p3[1]; bC[2]=t.x; bC[3]=t.y;
          ulonglong2 u2=p4[0]; q[0]=u2.x; q[1]=u2.y; }
#pragma unroll
        for(int i=0;i<8;i++){
#pragma unroll
            for(int j=0;j<4;j++) fma2(accP[i][j],aC[i],bC[j]);
            fma2(accQ[i][0],aS[i],q[0]);
            fma2(accQ[i][1],aS[i],q[1]);
        }
    }
}

// Stage1: A[img][u][w] = sum_h F[u][h]*x[img][w][h]  (cplx x real) — unchanged from R8
__global__ void __launch_bounds__(128) k_stage1(){
    __shared__ __align__(16) float AP[16*A_PITCH];
    __shared__ __align__(16) float BD[16*B_PITCH];
    const int img=blockIdx.z, n0=blockIdx.x*64, m0=blockIdx.y*64, tid=threadIdx.x;
    const int tn=tid&15, tm=tid>>4, lk=tid&15, lr=tid>>4;
    const float* Bg = g_xT + img*NH*NH;
    u64 acc[8][4];
#pragma unroll
    for(int i=0;i<8;i++)
#pragma unroll
        for(int j=0;j<4;j++) acc[i][j]=0ULL;
    float2 pa[8]; float pbx[8];
#pragma unroll
    for(int r=0;r<8;r++) pa[r]=g_Fp[(m0+lr+r*8)*NH+lk];
#pragma unroll
    for(int r=0;r<8;r++) pbx[r]=Bg[(n0+lr+r*8)*NH+lk];
    for(int t=0;t<8;t++){
#pragma unroll
        for(int r=0;r<8;r++) *(float2*)&AP[aoff(lk,lr+r*8)]=pa[r];
#pragma unroll
        for(int r=0;r<8;r++) *(float2*)&BD[boff(lk,lr+r*8)]=make_float2(pbx[r],pbx[r]);
        __syncthreads();
        if(t<7){
            int k0=(t+1)*16;
#pragma unroll
            for(int r=0;r<8;r++) pa[r]=g_Fp[(m0+lr+r*8)*NH+k0+lk];
#pragma unroll
            for(int r=0;r<8;r++) pbx[r]=Bg[(n0+lr+r*8)*NH+k0+lk];
        }
#pragma unroll 4
        for(int k=0;k<16;k++){
            u64 aP[8],bD[4];
            const ulonglong2* p1=(const ulonglong2*)&AP[k*A_PITCH+tm*20];
            const ulonglong2* p3=(const ulonglong2*)&BD[k*B_PITCH+tn*12];
#pragma unroll
            for(int q=0;q<4;q++){ ulonglong2 t2=p1[q]; aP[2*q]=t2.x; aP[2*q+1]=t2.y; }
            { ulonglong2 t2=p3[0]; bD[0]=t2.x; bD[1]=t2.y; t2=p3[1]; bD[2]=t2.x; bD[3]=t2.y; }
#pragma unroll
            for(int i=0;i<8;i++)
#pragma unroll
                for(int j=0;j<4;j++) fma2(acc[i][j],aP[i],bD[j]);
        }
        __syncthreads();
    }
    float2* C = g_A + img*NH*NH;
#pragma unroll
    for(int i=0;i<8;i++){ int m=m0+tm*8+i;
#pragma unroll
        for(int j=0;j<4;j++) C[m*NH+n0+tn*4+j]=up2(acc[i][j]); }
}

// Stage2 (Karatsuba): Xf[img][u][v] = sum_w A[img][u][w]*F[v][w]
__global__ void __launch_bounds__(128) k_stage2(){
    __shared__ __align__(16) float ACP[16*A_PITCH];
    __shared__ __align__(16) float ASD[16*A_PITCH];
    __shared__ __align__(16) float BCP[16*B_PITCH];
    __shared__ __align__(16) float SBV[16*SB_PITCH];
    const int img=blockIdx.z, n0=blockIdx.x*64, m0=blockIdx.y*64, tid=threadIdx.x;
    const int tn=tid&15, tm=tid>>4, lk=tid&15, lr=tid>>4;
    const float2* Ag = g_A + img*NH*NH;
    u64 accP[8][4], accQ[8][2];
#pragma unroll
    for(int i=0;i<8;i++){
#pragma unroll
        for(int j=0;j<4;j++) accP[i][j]=0ULL;
        accQ[i][0]=0ULL; accQ[i][1]=0ULL;
    }
    float2 pa[8], pb[8];
#pragma unroll
    for(int r=0;r<8;r++) pa[r]=Ag[(m0+lr+r*8)*NH+lk];
#pragma unroll
    for(int r=0;r<8;r++){ int v=n0+lr+r*8;
        pb[r]=(v<NF)? g_Fp[v*NH+lk] : make_float2(0.f,0.f); }
    for(int t=0;t<8;t++){
#pragma unroll
        for(int r=0;r<8;r++){ int m=lr+r*8;
            *(float2*)&ACP[aoff(lk,m)]=pa[r];
            float sa=pa[r].x+pa[r].y;
            *(float2*)&ASD[aoff(lk,m)]=make_float2(sa,sa); }
#pragma unroll
        for(int r=0;r<8;r++){ int n=lr+r*8;
            *(float2*)&BCP[boff(lk,n)]=pb[r];
            SBV[lk*SB_PITCH+n]=pb[r].x+pb[r].y; }
        __syncthreads();
        if(t<7){
            int k0=(t+1)*16;
#pragma unroll
            for(int r=0;r<8;r++) pa[r]=Ag[(m0+lr+r*8)*NH+k0+lk];
#pragma unroll
            for(int r=0;r<8;r++){ int v=n0+lr+r*8;
                pb[r]=(v<NF)? g_Fp[v*NH+k0+lk] : make_float2(0.f,0.f); }
        }
        kara_inner(ACP,ASD,BCP,SBV,accP,accQ,tm,tn);
        __syncthreads();
    }
    float2* C = g_Xf + img*NH*NF;
#pragma unroll
    for(int i=0;i<8;i++){ int m=m0+tm*8+i;
#pragma unroll
        for(int j=0;j<4;j++){ int n=n0+tn*4+j;
            if(n<NF){
                float2 p=up2(accP[i][j]);
                float2 qq=up2(accQ[i][j>>1]);
                float Qv=(j&1)? qq.y : qq.x;
                C[m*NF+n]=make_float2(p.x-p.y, Qv-p.x-p.y);
            } } }
}

// Stage3 (Karatsuba): St[img][w'][u] = sum_v (Xf[u][v]*Kh[c][u][v])*G[w'][v]
__global__ void __launch_bounds__(128) k_stage3(){
    __shared__ __align__(16) float ACP[16*A_PITCH];
    __shared__ __align__(16) float ASD[16*A_PITCH];
    __shared__ __align__(16) float BCP[16*B_PITCH];
    __shared__ __align__(16) float SBV[16*SB_PITCH];
    const int img=blockIdx.z, c=img&15, n0=blockIdx.x*64, m0=blockIdx.y*64, tid=threadIdx.x;
    const int tn=tid&15, tm=tid>>4, lk=tid&15, lr=tid>>4;
    const float2* Xg = g_Xf + img*NH*NF;
    const float2* Kg = g_Kh + c*NH*NF;
    u64 accP[8][4], accQ[8][2];
#pragma unroll
    for(int i=0;i<8;i++){
#pragma unroll
        for(int j=0;j<4;j++) accP[i][j]=0ULL;
        accQ[i][0]=0ULL; accQ[i][1]=0ULL;
    }
    float2 py[8], pb[8];
    {
        int kk=lk; bool ok=(kk<NF);
#pragma unroll
        for(int r=0;r<8;r++){
            float yr=0.f, yi=0.f;
            if(ok){ float2 x=Xg[(m0+lr+r*8)*NF+kk], h=Kg[(m0+lr+r*8)*NF+kk];
                yr=x.x*h.x-x.y*h.y; yi=x.x*h.y+x.y*h.x; }
            py[r]=make_float2(yr,yi);
        }
#pragma unroll
        for(int r=0;r<8;r++)
            pb[r]= ok ? g_Gp[(n0+lr+r*8)*NF+kk] : make_float2(0.f,0.f);
    }
    for(int t=0;t<16;t++){
#pragma unroll
        for(int r=0;r<8;r++){ int m=lr+r*8;
            *(float2*)&ACP[aoff(lk,m)]=py[r];
            float sa=py[r].x+py[r].y;
            *(float2*)&ASD[aoff(lk,m)]=make_float2(sa,sa); }
#pragma unroll
        for(int r=0;r<8;r++){ int n=lr+r*8;
            *(float2*)&BCP[boff(lk,n)]=pb[r];
            SBV[lk*SB_PITCH+n]=pb[r].x+pb[r].y; }
        __syncthreads();
        if(t<15){
            int kk=(t+1)*16+lk; bool ok=(kk<NF);
#pragma unroll
            for(int r=0;r<8;r++){
                float yr=0.f, yi=0.f;
                if(ok){ float2 x=Xg[(m0+lr+r*8)*NF+kk], h=Kg[(m0+lr+r*8)*NF+kk];
                    yr=x.x*h.x-x.y*h.y; yi=x.x*h.y+x.y*h.x; }
                py[r]=make_float2(yr,yi);
            }
#pragma unroll
            for(int r=0;r<8;r++)
                pb[r]= ok ? g_Gp[(n0+lr+r*8)*NF+kk] : make_float2(0.f,0.f);
        }
        kara_inner(ACP,ASD,BCP,SBV,accP,accQ,tm,tn);
        __syncthreads();
    }
    float2* C = g_St + img*NH*NH;
#pragma unroll
    for(int i=0;i<8;i++){ int m=m0+tm*8+i;
#pragma unroll
        for(int j=0;j<4;j++){ int n=n0+tn*4+j;
            float2 p=up2(accP[i][j]);
            float2 qq=up2(accQ[i][j>>1]);
            float Qv=(j&1)? qq.y : qq.x;
            C[n*NH+m]=make_float2(p.x-p.y, Qv-p.x-p.y);   // transposed store
        } }
}

// Stage4: out = bias + sum_u (Er*Sr - Ei*Si) — unchanged from R8
__global__ void __launch_bounds__(128) k_stage4(const float* __restrict__ bias,
                                               float* __restrict__ out){
    __shared__ __align__(16) float AE[16*A_PITCH];
    __shared__ __align__(16) float AN[16*A_PITCH];
    __shared__ __align__(16) float BR[16*68];
    __shared__ __align__(16) float BI[16*68];
    const int img=blockIdx.z, b2=img>>4, c=img&15;
    const int n0=blockIdx.x*64, m0=blockIdx.y*64, tid=threadIdx.x;
    const int tn=tid&15, tm=tid>>4, lk=tid&15, lr=tid>>4;
    const float2* Sg = g_St + img*NH*NH;
    u64 acc[8][2];
#pragma unroll
    for(int i=0;i<8;i++){ acc[i][0]=0ULL; acc[i][1]=0ULL; }
    float2 pe[8], pn[8], ps[8];
#pragma unroll
    for(int r=0;r<8;r++){ int m=m0+lr+r*8;
        pe[r]=g_E2r[m*NH+lk]; pn[r]=g_E2n[m*NH+lk]; }
#pragma unroll
    for(int r=0;r<8;r++) ps[r]=Sg[(n0+lr+r*8)*NH+lk];
    for(int t=0;t<8;t++){
#pragma unroll
        for(int r=0;r<8;r++){ int m=lr+r*8;
            *(float2*)&AE[aoff(lk,m)]=pe[r];
            *(float2*)&AN[aoff(lk,m)]=pn[r]; }
#pragma unroll
        for(int r=0;r<8;r++){ int n=lr+r*8;
            BR[lk*68+n]=ps[r].x; BI[lk*68+n]=ps[r].y; }
        __syncthreads();
        if(t<7){
            int k0=(t+1)*16;
#pragma unroll
            for(int r=0;r<8;r++){ int m=m0+lr+r*8;
                pe[r]=g_E2r[m*NH+k0+lk]; pn[r]=g_E2n[m*NH+k0+lk]; }
#pragma unroll
            for(int r=0;r<8;r++) ps[r]=Sg[(n0+lr+r*8)*NH+k0+lk];
        }
#pragma unroll 4
        for(int k=0;k<16;k++){
            u64 aE[8],aN2[8];
            const ulonglong2* p1=(const ulonglong2*)&AE[k*A_PITCH+tm*20];
            const ulonglong2* p2=(const ulonglong2*)&AN[k*A_PITCH+tm*20];
#pragma unroll
            for(int q=0;q<4;q++){
                ulonglong2 t2=p1[q]; aE[2*q]=t2.x; aE[2*q+1]=t2.y;
                ulonglong2 s2=p2[q]; aN2[2*q]=s2.x; aN2[2*q+1]=s2.y; }
            float4 br=*(const float4*)&BR[k*68+tn*4];
            float4 bi=*(const float4*)&BI[k*68+tn*4];
            u64 b0=pk2(br.x,br.y), b1=pk2(br.z,br.w);
            u64 c0=pk2(bi.x,bi.y), c1=pk2(bi.z,bi.w);
#pragma unroll
            for(int i=0;i<8;i++){
                fma2(acc[i][0],aE[i],b0); fma2(acc[i][0],aN2[i],c0);
                fma2(acc[i][1],aE[i],b1); fma2(acc[i][1],aN2[i],c1);
            }
        }
        __syncthreads();
    }
    float bv = bias[c];
#pragma unroll
    for(int i=0;i<8;i++){ int h=m0+tm*8+i;
#pragma unroll
        for(int j2=0;j2<2;j2++){
            float2 p=up2(acc[i][j2]);
            int w=n0+tn*4+j2*2;
            out[((size_t)((b2*NH+h)*NH+w  ))*NC+c]=p.x+bv;
            out[((size_t)((b2*NH+h)*NH+w+1))*NC+c]=p.y+bv;
        } }
}

extern "C" void kernel_launch(void* const* d_in, const int* in_sizes, int n_in,
                              void* d_out, int out_size){
    const float* inp  = (const float*)d_in[0];
    const float* kr   = (const float*)d_in[1];
    const float* ki   = (const float*)d_in[2];
    const float* bias = (const float*)d_in[3];
    float* out = (float*)d_out;

    const int twN = NF*NH + NH*NF + NH*NH;
    k_twiddles<<<(twN+255)/256, 256>>>();
    dim3 tg(8,4,4);
    k_transpose<<<tg, 256>>>(inp);
    k_keffkh<<<(NH*NF*NC+255)/256, 256>>>(kr, ki);

    dim3 blk(128);
    dim3 g1(2,2,NIMG); k_stage1<<<g1, blk>>>();
    dim3 g2(4,2,NIMG); k_stage2<<<g2, blk>>>();
    dim3 g3(2,2,NIMG); k_stage3<<<g3, blk>>>();
    dim3 g4(2,2,NIMG); k_stage4<<<g4, blk>>>(bias, out);
}

// round 12
// speedup vs baseline: 1.1406x; 1.0016x over previous
#include <cuda_runtime.h>

#define NF 255
#define NH 128
#define NC 16
#define NIMG 64
#define PI2 6.28318530717958647692f
typedef unsigned long long u64;

__device__ __forceinline__ void fma2(u64 &d, u64 a, u64 b){
    asm("fma.rn.f32x2 %0, %1, %2, %0;" : "+l"(d) : "l"(a), "l"(b));
}
__device__ __forceinline__ u64 pk2(float lo, float hi){
    u64 r; asm("mov.b64 %0, {%1,%2};" : "=l"(r) : "f"(lo), "f"(hi)); return r;
}
__device__ __forceinline__ float2 up2(u64 v){
    float2 f; asm("mov.b64 {%0,%1}, %2;" : "=f"(f.x), "=f"(f.y) : "l"(v)); return f;
}

// scratch (device globals: allocation-free rule)
__device__ float2 g_Fp[NF*NH];          // (cos,-sin)[v*128+h]
__device__ float2 g_Gp[NH*NF];          // (cos, sin)[w'*255+v], crop +63
__device__ float2 g_E2r[NH*NH];         // (Er,Er)   Er=cu*cos
__device__ float2 g_E2n[NH*NH];         // (-Ei,-Ei) Ei=cu*sin
__device__ float  g_xT[NIMG*NH*NH];     // [img][w][h]
__device__ float2 g_A [NIMG*NH*NH];     // [img][u][w]
__device__ float2 g_Xf[NIMG*NH*NF];     // [img][u][v]
__device__ float2 g_Kh[NC*NH*NF];       // [c][u][v] folded, scaled
__device__ float2 g_St[NIMG*NH*NH];     // [img][w'][u] (transposed)

__global__ void k_twiddles(){
    int i = blockIdx.x*blockDim.x + threadIdx.x;
    const float w0 = PI2/255.0f;
    if(i < NF*NH){
        int v=i/NH, h=i%NH; float a=w0*(float)((v*h)%NF);
        g_Fp[i]=make_float2(cosf(a),-sinf(a)); return;
    }
    int j=i-NF*NH;
    if(j < NH*NF){
        int wq=j/NF, v=j%NF; float a=w0*(float)((v*(wq+63))%NF);
        g_Gp[j]=make_float2(cosf(a),sinf(a)); return;
    }
    int e=j-NH*NF;
    if(e < NH*NH){
        int h=e/NH, u=e%NH; float a=w0*(float)((u*(h+63))%NF);
        float cu = u?2.f:1.f, er=cu*cosf(a), ei=cu*sinf(a);
        g_E2r[e]=make_float2(er,er); g_E2n[e]=make_float2(-ei,-ei);
    }
}

// in[b][h][w][c] -> g_xT[(b*16+c)][w][h], smem-staged
__global__ void k_transpose(const float* __restrict__ in){
    __shared__ float ts[NC*16*36];
    const int b=blockIdx.z, h0=blockIdx.y*32, w0=blockIdx.x*16, tid=threadIdx.x;
#pragma unroll
    for(int it=0;it<2;it++){
        int p=tid+it*256, h=p>>4, w=p&15;
        const float4* src=(const float4*)(in+(size_t)((b*NH+h0+h)*NH+w0+w)*NC);
#pragma unroll
        for(int q=0;q<4;q++){
            float4 v=src[q]; int cb=q*4;
            ts[(cb+0)*576+w*36+h]=v.x; ts[(cb+1)*576+w*36+h]=v.y;
            ts[(cb+2)*576+w*36+h]=v.z; ts[(cb+3)*576+w*36+h]=v.w;
        }
    }
    __syncthreads();
    int h4=(tid&7)*4;
#pragma unroll
    for(int it=0;it<8;it++){
        int q=(tid>>3)+it*32, c=q>>4, w=q&15;
        float4 v=*(const float4*)&ts[c*576+w*36+h4];
        *(float4*)&g_xT[(size_t)((b*NC+c)*NH+w0+w)*NH+h0+h4]=v;
    }
}

// fused Keff (sum over cout) + Hermitian fold + 1/255^2 scale
__global__ void k_keffkh(const float* __restrict__ kr, const float* __restrict__ ki){
    int idx = blockIdx.x*blockDim.x + threadIdx.x;
    if(idx >= NH*NF*NC) return;
    int c = idx&15, v = (idx>>4)%NF, u = idx/(16*NF);
    int u2=(NF-u)%NF, v2=(NF-v)%NF;
    size_t p1=((size_t)(u*NF+v)*NC+c)*16, p2=((size_t)(u2*NF+v2)*NC+c)*16;
    float sr1=0,si1=0,sr2=0,si2=0; const float4* a;
    a=(const float4*)(kr+p1);
#pragma unroll
    for(int j=0;j<4;j++){float4 t=a[j];sr1+=t.x+t.y+t.z+t.w;}
    a=(const float4*)(ki+p1);
#pragma unroll
    for(int j=0;j<4;j++){float4 t=a[j];si1+=t.x+t.y+t.z+t.w;}
    a=(const float4*)(kr+p2);
#pragma unroll
    for(int j=0;j<4;j++){float4 t=a[j];sr2+=t.x+t.y+t.z+t.w;}
    a=(const float4*)(ki+p2);
#pragma unroll
    for(int j=0;j<4;j++){float4 t=a[j];si2+=t.x+t.y+t.z+t.w;}
    const float s = 0.5f/65025.0f;
    g_Kh[(c*NH+u)*NF+v]=make_float2(s*(sr1+sr2), s*(si1-si2));
}

// ---------------------------------------------------------------------------
// GEMM: BM=64, BN=64, BK=16, 128 thr, 8m x 4n packed microtile, reg-prefetch,
// ping-pong double-buffered smem, ONE barrier per k-tile.
// Stages 2/3 use Karatsuba complex: 48 fma2/thread/k.
// ---------------------------------------------------------------------------
#define A_PITCH 164
#define B_PITCH 196
#define SB_PITCH 68
#define A_SZ (16*A_PITCH)
#define B_SZ (16*B_PITCH)
#define SB_SZ (16*SB_PITCH)
__device__ __forceinline__ int aoff(int k,int m){ return k*A_PITCH+(m>>3)*20+(m&7)*2; }
__device__ __forceinline__ int boff(int k,int n){ return k*B_PITCH+(n>>2)*12+(n&3)*2; }

// Karatsuba inner: accP[i][j] += (ar,ai)_i (x) (br,bi)_j ; accQ[i][jj] += (sa,sa)_i (x) (sb)
__device__ __forceinline__ void kara_inner(const float* ACP,const float* ASD,
        const float* BCP,const float* SBV,
        u64 (&accP)[8][4], u64 (&accQ)[8][2], int tm, int tn){
#pragma unroll 4
    for(int k=0;k<16;k++){
        u64 aC[8],aS[8],bC[4],q[2];
        const ulonglong2* p1=(const ulonglong2*)&ACP[k*A_PITCH+tm*20];
        const ulonglong2* p2=(const ulonglong2*)&ASD[k*A_PITCH+tm*20];
        const ulonglong2* p3=(const ulonglong2*)&BCP[k*B_PITCH+tn*12];
        const ulonglong2* p4=(const ulonglong2*)&SBV[k*SB_PITCH+tn*4];
#pragma unroll
        for(int r=0;r<4;r++){
            ulonglong2 t=p1[r]; aC[2*r]=t.x; aC[2*r+1]=t.y;
            ulonglong2 s=p2[r]; aS[2*r]=s.x; aS[2*r+1]=s.y;
        }
        { ulonglong2 t=p3[0]; bC[0]=t.x; bC[1]=t.y; t=p3[1]; bC[2]=t.x; bC[3]=t.y;
          ulonglong2 u2=p4[0]; q[0]=u2.x; q[1]=u2.y; }
#pragma unroll
        for(int i=0;i<8;i++){
#pragma unroll
            for(int j=0;j<4;j++) fma2(accP[i][j],aC[i],bC[j]);
            fma2(accQ[i][0],aS[i],q[0]);
            fma2(accQ[i][1],aS[i],q[1]);
        }
    }
}

// Stage1: A[img][u][w] = sum_h F[u][h]*x[img][w][h]  (cplx x real)
__global__ void __launch_bounds__(128) k_stage1(){
    __shared__ __align__(16) float AP[2*A_SZ];
    __shared__ __align__(16) float BD[2*B_SZ];
    const int img=blockIdx.z, n0=blockIdx.x*64, m0=blockIdx.y*64, tid=threadIdx.x;
    const int tn=tid&15, tm=tid>>4, lk=tid&15, lr=tid>>4;
    const float* Bg = g_xT + img*NH*NH;
    u64 acc[8][4];
#pragma unroll
    for(int i=0;i<8;i++)
#pragma unroll
        for(int j=0;j<4;j++) acc[i][j]=0ULL;
    float2 pa[8]; float pbx[8];
#pragma unroll
    for(int r=0;r<8;r++) pa[r]=g_Fp[(m0+lr+r*8)*NH+lk];
#pragma unroll
    for(int r=0;r<8;r++) pbx[r]=Bg[(n0+lr+r*8)*NH+lk];
    {
        float* APb=AP; float* BDb=BD;
#pragma unroll
        for(int r=0;r<8;r++) *(float2*)&APb[aoff(lk,lr+r*8)]=pa[r];
#pragma unroll
        for(int r=0;r<8;r++) *(float2*)&BDb[boff(lk,lr+r*8)]=make_float2(pbx[r],pbx[r]);
    }
    __syncthreads();
    for(int t=0;t<8;t++){
        if(t<7){
            int k0=(t+1)*16;
#pragma unroll
            for(int r=0;r<8;r++) pa[r]=g_Fp[(m0+lr+r*8)*NH+k0+lk];
#pragma unroll
            for(int r=0;r<8;r++) pbx[r]=Bg[(n0+lr+r*8)*NH+k0+lk];
        }
        const float* APc=AP+(t&1)*A_SZ; const float* BDc=BD+(t&1)*B_SZ;
#pragma unroll 4
        for(int k=0;k<16;k++){
            u64 aP[8],bD[4];
            const ulonglong2* p1=(const ulonglong2*)&APc[k*A_PITCH+tm*20];
            const ulonglong2* p3=(const ulonglong2*)&BDc[k*B_PITCH+tn*12];
#pragma unroll
            for(int q=0;q<4;q++){ ulonglong2 t2=p1[q]; aP[2*q]=t2.x; aP[2*q+1]=t2.y; }
            { ulonglong2 t2=p3[0]; bD[0]=t2.x; bD[1]=t2.y; t2=p3[1]; bD[2]=t2.x; bD[3]=t2.y; }
#pragma unroll
            for(int i=0;i<8;i++)
#pragma unroll
                for(int j=0;j<4;j++) fma2(acc[i][j],aP[i],bD[j]);
        }
        if(t<7){
            float* APn=AP+((t+1)&1)*A_SZ; float* BDn=BD+((t+1)&1)*B_SZ;
#pragma unroll
            for(int r=0;r<8;r++) *(float2*)&APn[aoff(lk,lr+r*8)]=pa[r];
#pragma unroll
            for(int r=0;r<8;r++) *(float2*)&BDn[boff(lk,lr+r*8)]=make_float2(pbx[r],pbx[r]);
        }
        __syncthreads();
    }
    float2* C = g_A + img*NH*NH;
#pragma unroll
    for(int i=0;i<8;i++){ int m=m0+tm*8+i;
#pragma unroll
        for(int j=0;j<4;j++) C[m*NH+n0+tn*4+j]=up2(acc[i][j]); }
}

// Stage2 (Karatsuba): Xf[img][u][v] = sum_w A[img][u][w]*F[v][w]
__global__ void __launch_bounds__(128) k_stage2(){
    extern __shared__ __align__(16) float sm[];
    float* ACPb=sm;                 // 2 x A_SZ
    float* ASDb=sm+2*A_SZ;          // 2 x A_SZ
    float* BCPb=sm+4*A_SZ;          // 2 x B_SZ
    float* SBVb=sm+4*A_SZ+2*B_SZ;   // 2 x SB_SZ
    const int img=blockIdx.z, n0=blockIdx.x*64, m0=blockIdx.y*64, tid=threadIdx.x;
    const int tn=tid&15, tm=tid>>4, lk=tid&15, lr=tid>>4;
    const float2* Ag = g_A + img*NH*NH;
    u64 accP[8][4], accQ[8][2];
#pragma unroll
    for(int i=0;i<8;i++){
#pragma unroll
        for(int j=0;j<4;j++) accP[i][j]=0ULL;
        accQ[i][0]=0ULL; accQ[i][1]=0ULL;
    }
    float2 pa[8], pb[8];
#pragma unroll
    for(int r=0;r<8;r++) pa[r]=Ag[(m0+lr+r*8)*NH+lk];
#pragma unroll
    for(int r=0;r<8;r++){ int v=n0+lr+r*8;
        pb[r]=(v<NF)? g_Fp[v*NH+lk] : make_float2(0.f,0.f); }
    {
#pragma unroll
        for(int r=0;r<8;r++){ int m=lr+r*8;
            *(float2*)&ACPb[aoff(lk,m)]=pa[r];
            float sa=pa[r].x+pa[r].y;
            *(float2*)&ASDb[aoff(lk,m)]=make_float2(sa,sa); }
#pragma unroll
        for(int r=0;r<8;r++){ int n=lr+r*8;
            *(float2*)&BCPb[boff(lk,n)]=pb[r];
            SBVb[lk*SB_PITCH+n]=pb[r].x+pb[r].y; }
    }
    __syncthreads();
    for(int t=0;t<8;t++){
        if(t<7){
            int k0=(t+1)*16;
#pragma unroll
            for(int r=0;r<8;r++) pa[r]=Ag[(m0+lr+r*8)*NH+k0+lk];
#pragma unroll
            for(int r=0;r<8;r++){ int v=n0+lr+r*8;
                pb[r]=(v<NF)? g_Fp[v*NH+k0+lk] : make_float2(0.f,0.f); }
        }
        int b=t&1;
        kara_inner(ACPb+b*A_SZ,ASDb+b*A_SZ,BCPb+b*B_SZ,SBVb+b*SB_SZ,accP,accQ,tm,tn);
        if(t<7){
            int b1=(t+1)&1;
            float* ACP=ACPb+b1*A_SZ; float* ASD=ASDb+b1*A_SZ;
            float* BCP=BCPb+b1*B_SZ; float* SBV=SBVb+b1*SB_SZ;
#pragma unroll
            for(int r=0;r<8;r++){ int m=lr+r*8;
                *(float2*)&ACP[aoff(lk,m)]=pa[r];
                float sa=pa[r].x+pa[r].y;
                *(float2*)&ASD[aoff(lk,m)]=make_float2(sa,sa); }
#pragma unroll
            for(int r=0;r<8;r++){ int n=lr+r*8;
                *(float2*)&BCP[boff(lk,n)]=pb[r];
                SBV[lk*SB_PITCH+n]=pb[r].x+pb[r].y; }
        }
        __syncthreads();
    }
    float2* C = g_Xf + img*NH*NF;
#pragma unroll
    for(int i=0;i<8;i++){ int m=m0+tm*8+i;
#pragma unroll
        for(int j=0;j<4;j++){ int n=n0+tn*4+j;
            if(n<NF){
                float2 p=up2(accP[i][j]);
                float2 qq=up2(accQ[i][j>>1]);
                float Qv=(j&1)? qq.y : qq.x;
                C[m*NF+n]=make_float2(p.x-p.y, Qv-p.x-p.y);
            } } }
}

// Stage3 (Karatsuba): St[img][w'][u] = sum_v (Xf[u][v]*Kh[c][u][v])*G[w'][v]
__global__ void __launch_bounds__(128) k_stage3(){
    extern __shared__ __align__(16) float sm[];
    float* ACPb=sm;
    float* ASDb=sm+2*A_SZ;
    float* BCPb=sm+4*A_SZ;
    float* SBVb=sm+4*A_SZ+2*B_SZ;
    const int img=blockIdx.z, c=img&15, n0=blockIdx.x*64, m0=blockIdx.y*64, tid=threadIdx.x;
    const int tn=tid&15, tm=tid>>4, lk=tid&15, lr=tid>>4;
    const float2* Xg = g_Xf + img*NH*NF;
    const float2* Kg = g_Kh + c*NH*NF;
    u64 accP[8][4], accQ[8][2];
#pragma unroll
    for(int i=0;i<8;i++){
#pragma unroll
        for(int j=0;j<4;j++) accP[i][j]=0ULL;
        accQ[i][0]=0ULL; accQ[i][1]=0ULL;
    }
    float2 py[8], pb[8];
    {
        int kk=lk; bool ok=(kk<NF);
#pragma unroll
        for(int r=0;r<8;r++){
            float yr=0.f, yi=0.f;
            if(ok){ float2 x=Xg[(m0+lr+r*8)*NF+kk], h=Kg[(m0+lr+r*8)*NF+kk];
                yr=x.x*h.x-x.y*h.y; yi=x.x*h.y+x.y*h.x; }
            py[r]=make_float2(yr,yi);
        }
#pragma unroll
        for(int r=0;r<8;r++)
            pb[r]= ok ? g_Gp[(n0+lr+r*8)*NF+kk] : make_float2(0.f,0.f);
    }
    {
#pragma unroll
        for(int r=0;r<8;r++){ int m=lr+r*8;
            *(float2*)&ACPb[aoff(lk,m)]=py[r];
            float sa=py[r].x+py[r].y;
            *(float2*)&ASDb[aoff(lk,m)]=make_float2(sa,sa); }
#pragma unroll
        for(int r=0;r<8;r++){ int n=lr+r*8;
            *(float2*)&BCPb[boff(lk,n)]=pb[r];
            SBVb[lk*SB_PITCH+n]=pb[r].x+pb[r].y; }
    }
    __syncthreads();
    for(int t=0;t<16;t++){
        if(t<15){
            int kk=(t+1)*16+lk; bool ok=(kk<NF);
#pragma unroll
            for(int r=0;r<8;r++){
                float yr=0.f, yi=0.f;
                if(ok){ float2 x=Xg[(m0+lr+r*8)*NF+kk], h=Kg[(m0+lr+r*8)*NF+kk];
                    yr=x.x*h.x-x.y*h.y; yi=x.x*h.y+x.y*h.x; }
                py[r]=make_float2(yr,yi);
            }
#pragma unroll
            for(int r=0;r<8;r++)
                pb[r]= ok ? g_Gp[(n0+lr+r*8)*NF+kk] : make_float2(0.f,0.f);
        }
        int b=t&1;
        kara_inner(ACPb+b*A_SZ,ASDb+b*A_SZ,BCPb+b*B_SZ,SBVb+b*SB_SZ,accP,accQ,tm,tn);
        if(t<15){
            int b1=(t+1)&1;
            float* ACP=ACPb+b1*A_SZ; float* ASD=ASDb+b1*A_SZ;
            float* BCP=BCPb+b1*B_SZ; float* SBV=SBVb+b1*SB_SZ;
#pragma unroll
            for(int r=0;r<8;r++){ int m=lr+r*8;
                *(float2*)&ACP[aoff(lk,m)]=py[r];
                float sa=py[r].x+py[r].y;
                *(float2*)&ASD[aoff(lk,m)]=make_float2(sa,sa); }
#pragma unroll
            for(int r=0;r<8;r++){ int n=lr+r*8;
                *(float2*)&BCP[boff(lk,n)]=pb[r];
                SBV[lk*SB_PITCH+n]=pb[r].x+pb[r].y; }
        }
        __syncthreads();
    }
    float2* C = g_St + img*NH*NH;
#pragma unroll
    for(int i=0;i<8;i++){ int m=m0+tm*8+i;
#pragma unroll
        for(int j=0;j<4;j++){ int n=n0+tn*4+j;
            float2 p=up2(accP[i][j]);
            float2 qq=up2(accQ[i][j>>1]);
            float Qv=(j&1)? qq.y : qq.x;
            C[n*NH+m]=make_float2(p.x-p.y, Qv-p.x-p.y);   // transposed store
        } }
}

// Stage4: out = bias + sum_u (Er*Sr - Ei*Si)
__global__ void __launch_bounds__(128) k_stage4(const float* __restrict__ bias,
                                               float* __restrict__ out){
    extern __shared__ __align__(16) float sm[];
    float* AEb=sm;                  // 2 x A_SZ
    float* ANb=sm+2*A_SZ;           // 2 x A_SZ
    float* BRb=sm+4*A_SZ;           // 2 x 1088
    float* BIb=sm+4*A_SZ+2*1088;    // 2 x 1088
    const int img=blockIdx.z, b2=img>>4, c=img&15;
    const int n0=blockIdx.x*64, m0=blockIdx.y*64, tid=threadIdx.x;
    const int tn=tid&15, tm=tid>>4, lk=tid&15, lr=tid>>4;
    const float2* Sg = g_St + img*NH*NH;
    u64 acc[8][2];
#pragma unroll
    for(int i=0;i<8;i++){ acc[i][0]=0ULL; acc[i][1]=0ULL; }
    float2 pe[8], pn[8], ps[8];
#pragma unroll
    for(int r=0;r<8;r++){ int m=m0+lr+r*8;
        pe[r]=g_E2r[m*NH+lk]; pn[r]=g_E2n[m*NH+lk]; }
#pragma unroll
    for(int r=0;r<8;r++) ps[r]=Sg[(n0+lr+r*8)*NH+lk];
    {
#pragma unroll
        for(int r=0;r<8;r++){ int m=lr+r*8;
            *(float2*)&AEb[aoff(lk,m)]=pe[r];
            *(float2*)&ANb[aoff(lk,m)]=pn[r]; }
#pragma unroll
        for(int r=0;r<8;r++){ int n=lr+r*8;
            BRb[lk*68+n]=ps[r].x; BIb[lk*68+n]=ps[r].y; }
    }
    __syncthreads();
    for(int t=0;t<8;t++){
        if(t<7){
            int k0=(t+1)*16;
#pragma unroll
            for(int r=0;r<8;r++){ int m=m0+lr+r*8;
                pe[r]=g_E2r[m*NH+k0+lk]; pn[r]=g_E2n[m*NH+k0+lk]; }
#pragma unroll
            for(int r=0;r<8;r++) ps[r]=Sg[(n0+lr+r*8)*NH+k0+lk];
        }
        const float* AE=AEb+(t&1)*A_SZ; const float* AN=ANb+(t&1)*A_SZ;
        const float* BR=BRb+(t&1)*1088; const float* BI=BIb+(t&1)*1088;
#pragma unroll 4
        for(int k=0;k<16;k++){
            u64 aE[8],aN2[8];
            const ulonglong2* p1=(const ulonglong2*)&AE[k*A_PITCH+tm*20];
            const ulonglong2* p2=(const ulonglong2*)&AN[k*A_PITCH+tm*20];
#pragma unroll
            for(int q=0;q<4;q++){
                ulonglong2 t2=p1[q]; aE[2*q]=t2.x; aE[2*q+1]=t2.y;
                ulonglong2 s2=p2[q]; aN2[2*q]=s2.x; aN2[2*q+1]=s2.y; }
            float4 br=*(const float4*)&BR[k*68+tn*4];
            float4 bi=*(const float4*)&BI[k*68+tn*4];
            u64 b0=pk2(br.x,br.y), b1=pk2(br.z,br.w);
            u64 c0=pk2(bi.x,bi.y), c1=pk2(bi.z,bi.w);
#pragma unroll
            for(int i=0;i<8;i++){
                fma2(acc[i][0],aE[i],b0); fma2(acc[i][0],aN2[i],c0);
                fma2(acc[i][1],aE[i],b1); fma2(acc[i][1],aN2[i],c1);
            }
        }
        if(t<7){
            int b1=(t+1)&1;
            float* AE2=AEb+b1*A_SZ; float* AN2b=ANb+b1*A_SZ;
            float* BR2=BRb+b1*1088; float* BI2=BIb+b1*1088;
#pragma unroll
            for(int r=0;r<8;r++){ int m=lr+r*8;
                *(float2*)&AE2[aoff(lk,m)]=pe[r];
                *(float2*)&AN2b[aoff(lk,m)]=pn[r]; }
#pragma unroll
            for(int r=0;r<8;r++){ int n=lr+r*8;
                BR2[lk*68+n]=ps[r].x; BI2[lk*68+n]=ps[r].y; }
        }
        __syncthreads();
    }
    float bv = bias[c];
#pragma unroll
    for(int i=0;i<8;i++){ int h=m0+tm*8+i;
#pragma unroll
        for(int j2=0;j2<2;j2++){
            float2 p=up2(acc[i][j2]);
            int w=n0+tn*4+j2*2;
            out[((size_t)((b2*NH+h)*NH+w  ))*NC+c]=p.x+bv;
            out[((size_t)((b2*NH+h)*NH+w+1))*NC+c]=p.y+bv;
        } }
}

extern "C" void kernel_launch(void* const* d_in, const int* in_sizes, int n_in,
                              void* d_out, int out_size){
    const float* inp  = (const float*)d_in[0];
    const float* kr   = (const float*)d_in[1];
    const float* ki   = (const float*)d_in[2];
    const float* bias = (const float*)d_in[3];
    float* out = (float*)d_out;

    const int SM23 = (4*A_SZ + 2*B_SZ + 2*SB_SZ)*4;   // 75776
    const int SM4  = (4*A_SZ + 4*1088)*4;             // 59392
    cudaFuncSetAttribute(k_stage2, cudaFuncAttributeMaxDynamicSharedMemorySize, SM23);
    cudaFuncSetAttribute(k_stage3, cudaFuncAttributeMaxDynamicSharedMemorySize, SM23);
    cudaFuncSetAttribute(k_stage4, cudaFuncAttributeMaxDynamicSharedMemorySize, SM4);

    const int twN = NF*NH + NH*NF + NH*NH;
    k_twiddles<<<(twN+255)/256, 256>>>();
    dim3 tg(8,4,4);
    k_transpose<<<tg, 256>>>(inp);
    k_keffkh<<<(NH*NF*NC+255)/256, 256>>>(kr, ki);

    dim3 blk(128);
    dim3 g1(2,2,NIMG); k_stage1<<<g1, blk>>>();
    dim3 g2(4,2,NIMG); k_stage2<<<g2, blk, SM23>>>();
    dim3 g3(2,2,NIMG); k_stage3<<<g3, blk, SM23>>>();
    dim3 g4(2,2,NIMG); k_stage4<<<g4, blk, SM4>>>(bias, out);
}

// round 13
// speedup vs baseline: 1.2587x; 1.1035x over previous
#include <cuda_runtime.h>
#include <cstdint>

#define NF 255
#define NH 128
#define NC 16
#define NIMG 64
#define PI2 6.28318530717958647692f

__device__ __forceinline__ uint32_t f2tf(float x){
    uint32_t r; asm("cvt.rna.tf32.f32 %0, %1;" : "=r"(r) : "f"(x)); return r;
}
// split x into (hi,lo) tf32 pair stored as floats
__device__ __forceinline__ float2 spl(float x){
    uint32_t h = f2tf(x);
    float hf = __uint_as_float(h);
    uint32_t l = f2tf(x - hf);
    return make_float2(hf, __uint_as_float(l));
}
__device__ __forceinline__ void mmaT(float* c, const uint32_t* a, const uint32_t* b){
    asm("mma.sync.aligned.m16n8k8.row.col.f32.tf32.tf32.f32 "
        "{%0,%1,%2,%3},{%4,%5,%6,%7},{%8,%9},{%0,%1,%2,%3};"
        : "+f"(c[0]),"+f"(c[1]),"+f"(c[2]),"+f"(c[3])
        : "r"(a[0]),"r"(a[1]),"r"(a[2]),"r"(a[3]),"r"(b[0]),"r"(b[1]));
}
// 3xTF32 product: C += A*B with error compensation
__device__ __forceinline__ void mma3(float* c, const uint32_t* ah, const uint32_t* al,
                                     const uint32_t* bh, const uint32_t* bl){
    mmaT(c, ah, bh); mmaT(c, ah, bl); mmaT(c, al, bh);
}
// A fragment (m16 x k8) from (hi,lo) float2 plane, pitch 20
__device__ __forceinline__ void ldA(uint32_t* h, uint32_t* l, const float2* P, int m, int k){
    float2 v0=P[m*20+k],     v1=P[(m+8)*20+k];
    float2 v2=P[m*20+k+4],   v3=P[(m+8)*20+k+4];
    h[0]=__float_as_uint(v0.x); l[0]=__float_as_uint(v0.y);
    h[1]=__float_as_uint(v1.x); l[1]=__float_as_uint(v1.y);
    h[2]=__float_as_uint(v2.x); l[2]=__float_as_uint(v2.y);
    h[3]=__float_as_uint(v3.x); l[3]=__float_as_uint(v3.y);
}
// B fragment (k8 x n8) from (hi,lo) float2 plane, pitch 20
__device__ __forceinline__ void ldB(uint32_t* h, uint32_t* l, const float2* P, int n, int k){
    float2 v0=P[n*20+k], v1=P[n*20+k+4];
    h[0]=__float_as_uint(v0.x); l[0]=__float_as_uint(v0.y);
    h[1]=__float_as_uint(v1.x); l[1]=__float_as_uint(v1.y);
}

// scratch (device globals: allocation-free rule)
__device__ float2 g_Fp[NF*NH];          // (cos,-sin)[v*128+h]
__device__ float2 g_Gp[NH*NF];          // (cos, sin)[w'*255+v], crop +63
__device__ float2 g_Ep[NH*NH];          // (cu*cos, -cu*sin)[h*128+u]
__device__ float  g_xT[NIMG*NH*NH];     // [img][w][h]
__device__ float2 g_A [NIMG*NH*NH];     // [img][u][w]
__device__ float2 g_Xf[NIMG*NH*NF];     // [img][u][v]
__device__ float2 g_Kh[NC*NH*NF];       // [c][u][v] folded, scaled
__device__ float2 g_St[NIMG*NH*NH];     // [img][w'][u] (transposed)

__global__ void k_twiddles(){
    int i = blockIdx.x*blockDim.x + threadIdx.x;
    const float w0 = PI2/255.0f;
    if(i < NF*NH){
        int v=i/NH, h=i%NH; float a=w0*(float)((v*h)%NF);
        g_Fp[i]=make_float2(cosf(a),-sinf(a)); return;
    }
    int j=i-NF*NH;
    if(j < NH*NF){
        int wq=j/NF, v=j%NF; float a=w0*(float)((v*(wq+63))%NF);
        g_Gp[j]=make_float2(cosf(a),sinf(a)); return;
    }
    int e=j-NH*NF;
    if(e < NH*NH){
        int h=e/NH, u=e%NH; float a=w0*(float)((u*(h+63))%NF);
        float cu = u?2.f:1.f;
        g_Ep[e]=make_float2(cu*cosf(a), -cu*sinf(a));
    }
}

// in[b][h][w][c] -> g_xT[(b*16+c)][w][h], smem-staged
__global__ void k_transpose(const float* __restrict__ in){
    __shared__ float ts[NC*16*36];
    const int b=blockIdx.z, h0=blockIdx.y*32, w0=blockIdx.x*16, tid=threadIdx.x;
#pragma unroll
    for(int it=0;it<2;it++){
        int p=tid+it*256, h=p>>4, w=p&15;
        const float4* src=(const float4*)(in+(size_t)((b*NH+h0+h)*NH+w0+w)*NC);
#pragma unroll
        for(int q=0;q<4;q++){
            float4 v=src[q]; int cb=q*4;
            ts[(cb+0)*576+w*36+h]=v.x; ts[(cb+1)*576+w*36+h]=v.y;
            ts[(cb+2)*576+w*36+h]=v.z; ts[(cb+3)*576+w*36+h]=v.w;
        }
    }
    __syncthreads();
    int h4=(tid&7)*4;
#pragma unroll
    for(int it=0;it<8;it++){
        int q=(tid>>3)+it*32, c=q>>4, w=q&15;
        float4 v=*(const float4*)&ts[c*576+w*36+h4];
        *(float4*)&g_xT[(size_t)((b*NC+c)*NH+w0+w)*NH+h0+h4]=v;
    }
}

// fused Keff (sum over cout) + Hermitian fold + 1/255^2 scale
__global__ void k_keffkh(const float* __restrict__ kr, const float* __restrict__ ki){
    int idx = blockIdx.x*blockDim.x + threadIdx.x;
    if(idx >= NH*NF*NC) return;
    int c = idx&15, v = (idx>>4)%NF, u = idx/(16*NF);
    int u2=(NF-u)%NF, v2=(NF-v)%NF;
    size_t p1=((size_t)(u*NF+v)*NC+c)*16, p2=((size_t)(u2*NF+v2)*NC+c)*16;
    float sr1=0,si1=0,sr2=0,si2=0; const float4* a;
    a=(const float4*)(kr+p1);
#pragma unroll
    for(int j=0;j<4;j++){float4 t=a[j];sr1+=t.x+t.y+t.z+t.w;}
    a=(const float4*)(ki+p1);
#pragma unroll
    for(int j=0;j<4;j++){float4 t=a[j];si1+=t.x+t.y+t.z+t.w;}
    a=(const float4*)(kr+p2);
#pragma unroll
    for(int j=0;j<4;j++){float4 t=a[j];sr2+=t.x+t.y+t.z+t.w;}
    a=(const float4*)(ki+p2);
#pragma unroll
    for(int j=0;j<4;j++){float4 t=a[j];si2+=t.x+t.y+t.z+t.w;}
    const float s = 0.5f/65025.0f;
    g_Kh[(c*NH+u)*NF+v]=make_float2(s*(sr1+sr2), s*(si1-si2));
}

// ---------------------------------------------------------------------------
// Tensor-core GEMM stages: CTA 64m x 64n, 128 thr (4 warps x 16m stripe),
// BK=16, smem planes hold (tf32-hi, tf32-lo) pairs, 3xTF32 mma.sync m16n8k8.
// C[m,n] = sum_k A[m,k]*B[n,k] (A row-major, B[n][k] = col-major k x n).
// ---------------------------------------------------------------------------

// Stage1: A[img][u][w] = sum_h F[u][h]*x[img][w][h]  (cplx A, real B)
__global__ void __launch_bounds__(128) k_stage1(){
    __shared__ float2 AR[64*20], AI[64*20], BRp[64*20];
    const int img=blockIdx.z, n0=blockIdx.x*64, m0=blockIdx.y*64, tid=threadIdx.x;
    const int lane=tid&31, gl=lane>>2, cl=lane&3, mw=(tid>>5)*16;
    const int lk=tid&15, lr=tid>>4;
    const float* Bg = g_xT + img*NH*NH;
    float cR[8][4], cI[8][4];
#pragma unroll
    for(int i=0;i<8;i++)
#pragma unroll
        for(int j=0;j<4;j++){ cR[i][j]=0.f; cI[i][j]=0.f; }
    float2 pa[8]; float pbx[8];
#pragma unroll
    for(int r=0;r<8;r++) pa[r]=g_Fp[(m0+lr+r*8)*NH+lk];
#pragma unroll
    for(int r=0;r<8;r++) pbx[r]=Bg[(n0+lr+r*8)*NH+lk];
    for(int t=0;t<8;t++){
#pragma unroll
        for(int r=0;r<8;r++){ int m=lr+r*8;
            AR[m*20+lk]=spl(pa[r].x); AI[m*20+lk]=spl(pa[r].y);
            BRp[m*20+lk]=spl(pbx[r]); }
        __syncthreads();
        if(t<7){
            int k0=(t+1)*16;
#pragma unroll
            for(int r=0;r<8;r++) pa[r]=g_Fp[(m0+lr+r*8)*NH+k0+lk];
#pragma unroll
            for(int r=0;r<8;r++) pbx[r]=Bg[(n0+lr+r*8)*NH+k0+lk];
        }
#pragma unroll
        for(int s=0;s<16;s+=8){
            uint32_t arh[4],arl[4],aih[4],ail[4];
            ldA(arh,arl,AR,mw+gl,s+cl);
            ldA(aih,ail,AI,mw+gl,s+cl);
#pragma unroll
            for(int nb=0;nb<8;nb++){
                uint32_t brh[2],brl[2];
                ldB(brh,brl,BRp,nb*8+gl,s+cl);
                mma3(cR[nb],arh,arl,brh,brl);
                mma3(cI[nb],aih,ail,brh,brl);
            }
        }
        __syncthreads();
    }
    float2* C = g_A + img*NH*NH;
#pragma unroll
    for(int nb=0;nb<8;nb++){
        int n = n0+nb*8+2*cl, m = m0+mw+gl;
        C[m*NH+n]       = make_float2(cR[nb][0],cI[nb][0]);
        C[m*NH+n+1]     = make_float2(cR[nb][1],cI[nb][1]);
        C[(m+8)*NH+n]   = make_float2(cR[nb][2],cI[nb][2]);
        C[(m+8)*NH+n+1] = make_float2(cR[nb][3],cI[nb][3]);
    }
}

// Stage2: Xf[img][u][v] = sum_w A[img][u][w]*F[v][w]  (cplx x cplx)
__global__ void __launch_bounds__(128) k_stage2(){
    __shared__ float2 AR[64*20], AI[64*20], BR[64*20], BI[64*20];
    const int img=blockIdx.z, n0=blockIdx.x*64, m0=blockIdx.y*64, tid=threadIdx.x;
    const int lane=tid&31, gl=lane>>2, cl=lane&3, mw=(tid>>5)*16;
    const int lk=tid&15, lr=tid>>4;
    const float2* Ag = g_A + img*NH*NH;
    float cR[8][4], cI[8][4];
#pragma unroll
    for(int i=0;i<8;i++)
#pragma unroll
        for(int j=0;j<4;j++){ cR[i][j]=0.f; cI[i][j]=0.f; }
    float2 pa[8], pb[8];
#pragma unroll
    for(int r=0;r<8;r++) pa[r]=Ag[(m0+lr+r*8)*NH+lk];
#pragma unroll
    for(int r=0;r<8;r++){ int v=n0+lr+r*8;
        pb[r]=(v<NF)? g_Fp[v*NH+lk] : make_float2(0.f,0.f); }
    for(int t=0;t<8;t++){
#pragma unroll
        for(int r=0;r<8;r++){ int m=lr+r*8;
            AR[m*20+lk]=spl(pa[r].x); AI[m*20+lk]=spl(pa[r].y);
            BR[m*20+lk]=spl(pb[r].x); BI[m*20+lk]=spl(pb[r].y); }
        __syncthreads();
        if(t<7){
            int k0=(t+1)*16;
#pragma unroll
            for(int r=0;r<8;r++) pa[r]=Ag[(m0+lr+r*8)*NH+k0+lk];
#pragma unroll
            for(int r=0;r<8;r++){ int v=n0+lr+r*8;
                pb[r]=(v<NF)? g_Fp[v*NH+k0+lk] : make_float2(0.f,0.f); }
        }
#pragma unroll
        for(int s=0;s<16;s+=8){
            uint32_t arh[4],arl[4],aih[4],ail[4],anh[4],anl[4];
            ldA(arh,arl,AR,mw+gl,s+cl);
            ldA(aih,ail,AI,mw+gl,s+cl);
#pragma unroll
            for(int q=0;q<4;q++){ anh[q]=aih[q]^0x80000000u; anl[q]=ail[q]^0x80000000u; }
#pragma unroll
            for(int nb=0;nb<8;nb++){
                uint32_t brh[2],brl[2],bih[2],bil[2];
                ldB(brh,brl,BR,nb*8+gl,s+cl);
                ldB(bih,bil,BI,nb*8+gl,s+cl);
                mma3(cR[nb],arh,arl,brh,brl);   // + Ar*Br
                mma3(cR[nb],anh,anl,bih,bil);   // - Ai*Bi
                mma3(cI[nb],arh,arl,bih,bil);   // + Ar*Bi
                mma3(cI[nb],aih,ail,brh,brl);   // + Ai*Br
            }
        }
        __syncthreads();
    }
    float2* C = g_Xf + img*NH*NF;
#pragma unroll
    for(int nb=0;nb<8;nb++){
        int n = n0+nb*8+2*cl, m = m0+mw+gl;
        if(n<NF){
            C[m*NF+n]     = make_float2(cR[nb][0],cI[nb][0]);
            C[(m+8)*NF+n] = make_float2(cR[nb][2],cI[nb][2]);
        }
        if(n+1<NF){
            C[m*NF+n+1]     = make_float2(cR[nb][1],cI[nb][1]);
            C[(m+8)*NF+n+1] = make_float2(cR[nb][3],cI[nb][3]);
        }
    }
}

// Stage3: St[img][w'][u] = sum_v (Xf[u][v]*Kh[c][u][v])*G[w'][v]
__global__ void __launch_bounds__(128) k_stage3(){
    __shared__ float2 AR[64*20], AI[64*20], BR[64*20], BI[64*20];
    const int img=blockIdx.z, c=img&15, n0=blockIdx.x*64, m0=blockIdx.y*64, tid=threadIdx.x;
    const int lane=tid&31, gl=lane>>2, cl=lane&3, mw=(tid>>5)*16;
    const int lk=tid&15, lr=tid>>4;
    const float2* Xg = g_Xf + img*NH*NF;
    const float2* Kg = g_Kh + c*NH*NF;
    float cR[8][4], cI[8][4];
#pragma unroll
    for(int i=0;i<8;i++)
#pragma unroll
        for(int j=0;j<4;j++){ cR[i][j]=0.f; cI[i][j]=0.f; }
    float2 py[8], pb[8];
    {
        int kk=lk; bool ok=(kk<NF);
#pragma unroll
        for(int r=0;r<8;r++){
            float yr=0.f, yi=0.f;
            if(ok){ float2 x=Xg[(m0+lr+r*8)*NF+kk], h=Kg[(m0+lr+r*8)*NF+kk];
                yr=x.x*h.x-x.y*h.y; yi=x.x*h.y+x.y*h.x; }
            py[r]=make_float2(yr,yi);
        }
#pragma unroll
        for(int r=0;r<8;r++)
            pb[r]= ok ? g_Gp[(n0+lr+r*8)*NF+kk] : make_float2(0.f,0.f);
    }
    for(int t=0;t<16;t++){
#pragma unroll
        for(int r=0;r<8;r++){ int m=lr+r*8;
            AR[m*20+lk]=spl(py[r].x); AI[m*20+lk]=spl(py[r].y);
            BR[m*20+lk]=spl(pb[r].x); BI[m*20+lk]=spl(pb[r].y); }
        __syncthreads();
        if(t<15){
            int kk=(t+1)*16+lk; bool ok=(kk<NF);
#pragma unroll
            for(int r=0;r<8;r++){
                float yr=0.f, yi=0.f;
                if(ok){ float2 x=Xg[(m0+lr+r*8)*NF+kk], h=Kg[(m0+lr+r*8)*NF+kk];
                    yr=x.x*h.x-x.y*h.y; yi=x.x*h.y+x.y*h.x; }
                py[r]=make_float2(yr,yi);
            }
#pragma unroll
            for(int r=0;r<8;r++)
                pb[r]= ok ? g_Gp[(n0+lr+r*8)*NF+kk] : make_float2(0.f,0.f);
        }
#pragma unroll
        for(int s=0;s<16;s+=8){
            uint32_t arh[4],arl[4],aih[4],ail[4],anh[4],anl[4];
            ldA(arh,arl,AR,mw+gl,s+cl);
            ldA(aih,ail,AI,mw+gl,s+cl);
#pragma unroll
            for(int q=0;q<4;q++){ anh[q]=aih[q]^0x80000000u; anl[q]=ail[q]^0x80000000u; }
#pragma unroll
            for(int nb=0;nb<8;nb++){
                uint32_t brh[2],brl[2],bih[2],bil[2];
                ldB(brh,brl,BR,nb*8+gl,s+cl);
                ldB(bih,bil,BI,nb*8+gl,s+cl);
                mma3(cR[nb],arh,arl,brh,brl);
                mma3(cR[nb],anh,anl,bih,bil);
                mma3(cI[nb],arh,arl,bih,bil);
                mma3(cI[nb],aih,ail,brh,brl);
            }
        }
        __syncthreads();
    }
    float2* C = g_St + img*NH*NH;
#pragma unroll
    for(int nb=0;nb<8;nb++){            // store transposed: C[w'][u]
        int n = n0+nb*8+2*cl, m = m0+mw+gl;
        C[n*NH+m]       = make_float2(cR[nb][0],cI[nb][0]);
        C[(n+1)*NH+m]   = make_float2(cR[nb][1],cI[nb][1]);
        C[n*NH+m+8]     = make_float2(cR[nb][2],cI[nb][2]);
        C[(n+1)*NH+m+8] = make_float2(cR[nb][3],cI[nb][3]);
    }
}

// Stage4: out[b][h][w][c] = bias[c] + sum_u (Er[h][u]*Sr[w][u] - Ei[h][u]*Si[w][u])
__global__ void __launch_bounds__(128) k_stage4(const float* __restrict__ bias,
                                               float* __restrict__ out){
    __shared__ float2 AE[64*20], AN[64*20], BR[64*20], BI[64*20];
    const int img=blockIdx.z, b2=img>>4, c=img&15;
    const int n0=blockIdx.x*64, m0=blockIdx.y*64, tid=threadIdx.x;
    const int lane=tid&31, gl=lane>>2, cl=lane&3, mw=(tid>>5)*16;
    const int lk=tid&15, lr=tid>>4;
    const float2* Sg = g_St + img*NH*NH;
    float cO[8][4];
#pragma unroll
    for(int i=0;i<8;i++)
#pragma unroll
        for(int j=0;j<4;j++) cO[i][j]=0.f;
    float2 pe[8], ps[8];
#pragma unroll
    for(int r=0;r<8;r++) pe[r]=g_Ep[(m0+lr+r*8)*NH+lk];
#pragma unroll
    for(int r=0;r<8;r++) ps[r]=Sg[(n0+lr+r*8)*NH+lk];
    for(int t=0;t<8;t++){
#pragma unroll
        for(int r=0;r<8;r++){ int m=lr+r*8;
            AE[m*20+lk]=spl(pe[r].x); AN[m*20+lk]=spl(pe[r].y);   // (er, -ei)
            BR[m*20+lk]=spl(ps[r].x); BI[m*20+lk]=spl(ps[r].y); }
        __syncthreads();
        if(t<7){
            int k0=(t+1)*16;
#pragma unroll
            for(int r=0;r<8;r++) pe[r]=g_Ep[(m0+lr+r*8)*NH+k0+lk];
#pragma unroll
            for(int r=0;r<8;r++) ps[r]=Sg[(n0+lr+r*8)*NH+k0+lk];
        }
#pragma unroll
        for(int s=0;s<16;s+=8){
            uint32_t aeh[4],ael[4],anh[4],anl[4];
            ldA(aeh,ael,AE,mw+gl,s+cl);
            ldA(anh,anl,AN,mw+gl,s+cl);
#pragma unroll
            for(int nb=0;nb<8;nb++){
                uint32_t brh[2],brl[2],bih[2],bil[2];
                ldB(brh,brl,BR,nb*8+gl,s+cl);
                ldB(bih,bil,BI,nb*8+gl,s+cl);
                mma3(cO[nb],aeh,ael,brh,brl);   // + er*Sr
                mma3(cO[nb],anh,anl,bih,bil);   // + (-ei)*Si
            }
        }
        __syncthreads();
    }
    float bv = bias[c];
#pragma unroll
    for(int nb=0;nb<8;nb++){
        int w = n0+nb*8+2*cl, h = m0+mw+gl;
        out[((size_t)((b2*NH+h)*NH+w  ))*NC+c] = cO[nb][0]+bv;
        out[((size_t)((b2*NH+h)*NH+w+1))*NC+c] = cO[nb][1]+bv;
        out[((size_t)((b2*NH+h+8)*NH+w  ))*NC+c] = cO[nb][2]+bv;
        out[((size_t)((b2*NH+h+8)*NH+w+1))*NC+c] = cO[nb][3]+bv;
    }
}

extern "C" void kernel_launch(void* const* d_in, const int* in_sizes, int n_in,
                              void* d_out, int out_size){
    const float* inp  = (const float*)d_in[0];
    const float* kr   = (const float*)d_in[1];
    const float* ki   = (const float*)d_in[2];
    const float* bias = (const float*)d_in[3];
    float* out = (float*)d_out;

    const int twN = NF*NH + NH*NF + NH*NH;
    k_twiddles<<<(twN+255)/256, 256>>>();
    dim3 tg(8,4,4);
    k_transpose<<<tg, 256>>>(inp);
    k_keffkh<<<(NH*NF*NC+255)/256, 256>>>(kr, ki);

    dim3 blk(128);
    dim3 g1(2,2,NIMG); k_stage1<<<g1, blk>>>();
    dim3 g2(4,2,NIMG); k_stage2<<<g2, blk>>>();
    dim3 g3(2,2,NIMG); k_stage3<<<g3, blk>>>();
    dim3 g4(2,2,NIMG); k_stage4<<<g4, blk>>>(bias, out);
}